// round 14
// baseline (speedup 1.0000x reference)
#include <cuda_runtime.h>
#include <cuda_bf16.h>
#include <math.h>
#include <stdint.h>

// Problem worst-case sizing
#define MAXB 8
#define MAXS 8192
#define MAXH 768
#define MAXBS (MAXB * MAXS)          // 65536 rows

// ---------------- static device scratch ----------------
__device__ __nv_bfloat16 g_actb[(size_t)MAXBS * MAXH];      // bf16 silu activations (~100 MB)
__device__ __nv_bfloat16 g_wb[(size_t)(2 * MAXH) * MAXH];   // bf16 W (~2.4 MB)
__device__ int   g_tapPos[(size_t)MAXH * MAXS];
__device__ float g_tapVal[(size_t)MAXH * MAXS];
__device__ int   g_tapCnt[MAXH];

#define LAM 0.1f

#define CP_ASYNC16(dst, src) \
    asm volatile("cp.async.cg.shared.global [%0], [%1], 16;" :: "r"(dst), "l"(src) : "memory")

__device__ __forceinline__ uint32_t smem_u32(const void* p) {
    uint32_t a;
    asm("{ .reg .u64 t; cvta.to.shared.u64 t, %1; cvt.u32.u64 %0, t; }" : "=r"(a) : "l"(p));
    return a;
}

#define LDSM_X4(r, addr)                                                        \
    asm volatile("ldmatrix.sync.aligned.m8n8.x4.shared.b16 {%0,%1,%2,%3}, [%4];" \
        : "=r"((r)[0]), "=r"((r)[1]), "=r"((r)[2]), "=r"((r)[3]) : "r"(addr))

// mma m16n8k16 bf16, fp32 accum
#define MMA_BF16(c, a, b0, b1)                                                  \
    asm volatile(                                                               \
        "mma.sync.aligned.m16n8k16.row.col.f32.bf16.bf16.f32 "                  \
        "{%0,%1,%2,%3}, {%4,%5,%6,%7}, {%8,%9}, {%0,%1,%2,%3};"                 \
        : "+f"((c)[0]), "+f"((c)[1]), "+f"((c)[2]), "+f"((c)[3])                \
        : "r"((a)[0]), "r"((a)[1]), "r"((a)[2]), "r"((a)[3]),                   \
          "r"(b0), "r"(b1))

// ---------------- 1) threshold kernel -> sparse tap lists --------------------
__global__ void build_taps_kernel(const float* __restrict__ kern, int L) {
    int h = blockIdx.x;
    if (threadIdx.x == 0) g_tapCnt[h] = 0;
    __syncthreads();
    const float* kr = kern + (size_t)h * L;
    for (int j = threadIdx.x; j < L; j += blockDim.x) {
        float kv = kr[j];
        float a = fabsf(kv) - LAM;
        if (a > 0.0f) {
            float val = copysignf(a, kv);
            int idx = atomicAdd(&g_tapCnt[h], 1);
            g_tapPos[(size_t)h * L + idx] = j;
            g_tapVal[(size_t)h * L + idx] = val;
        }
    }
}

// ---------------- 1b) convert W to bf16 ----------------
__global__ void conv_w_kernel(const float* __restrict__ W, __nv_bfloat16* __restrict__ Wb, int n4) {
    int i = blockIdx.x * blockDim.x + threadIdx.x;
    if (i >= n4) return;
    float4 v = *(const float4*)(W + i * 4);
    __nv_bfloat162* o = (__nv_bfloat162*)(Wb + i * 4);
    o[0] = __floats2bfloat162_rn(v.x, v.y);
    o[1] = __floats2bfloat162_rn(v.z, v.w);
}

// ---------------- 2) activation: sparse conv + skip + silu -> bf16 -----------
__global__ void act_kernel(const float* __restrict__ x, const float* __restrict__ D,
                           __nv_bfloat16* __restrict__ act, int total4, int H, int S) {
    int i = blockIdx.x * blockDim.x + threadIdx.x;
    if (i >= total4) return;
    int base = i * 4;
    int h  = base % H;
    int bl = base / H;
    float4 xv = *(const float4*)(x + base);
    float4 dv = *(const float4*)(D + h);
    float v[4] = {xv.x * dv.x, xv.y * dv.y, xv.z * dv.z, xv.w * dv.w};
    int cnt[4] = {g_tapCnt[h], g_tapCnt[h + 1], g_tapCnt[h + 2], g_tapCnt[h + 3]};
    if (cnt[0] | cnt[1] | cnt[2] | cnt[3]) {
        int l = bl % S;
        int b = bl / S;
        const float* xb = x + (size_t)b * S * H;
        #pragma unroll
        for (int q = 0; q < 4; q++) {
            const int*   tp = g_tapPos + (size_t)(h + q) * S;
            const float* tv = g_tapVal + (size_t)(h + q) * S;
            for (int t = 0; t < cnt[q]; t++) {
                int j = tp[t];
                if (j <= l) v[q] += tv[t] * xb[(size_t)(l - j) * H + h + q];
            }
        }
    }
    float o0 = v[0] / (1.0f + expf(-v[0]));
    float o1 = v[1] / (1.0f + expf(-v[1]));
    float o2 = v[2] / (1.0f + expf(-v[2]));
    float o3 = v[3] / (1.0f + expf(-v[3]));
    __nv_bfloat162* op = (__nv_bfloat162*)(act + base);
    op[0] = __floats2bfloat162_rn(o0, o1);
    op[1] = __floats2bfloat162_rn(o2, o3);
}

// ---------------- 3) bf16 mma.sync GEMM + GLU + residual ---------------------
// CTA: 128 M-rows x 64 out-cols, 128 threads = 4 warps (2 m x 2 n), 2 CTAs/SM.
// Warp tile: 64 M-rows x 64 B-rows (32 out-cols) -> 8 LDSM per 32 MMAs.
// B tile = 128 interleaved rows (even=Wa[n0+j/2], odd=Wg[n0+j/2]).
// K-chunk = 64 halves, 3-stage cp.async pipeline, 1 barrier/chunk,
// ks-level register double buffering of A and B fragments.
#define CTA_M 128
#define CTA_C 64
#define KC    64                                   // bf16 halves per chunk
#define ABUF_BYTES (CTA_M * KC * 2)                // 16 KB
#define BBUF_BYTES (2 * CTA_C * KC * 2)            // 16 KB
#define BUF_BYTES  (ABUF_BYTES + BBUF_BYTES)       // 32 KB
#define NSTAGE 3
#define SMEM_GEMM  (NSTAGE * BUF_BYTES)            // 96 KB

__global__ __launch_bounds__(128, 2)
void gemm_glu_mma(const __nv_bfloat16* __restrict__ A, const __nv_bfloat16* __restrict__ W,
                  const float* __restrict__ bias, const float* __restrict__ x,
                  float* __restrict__ out, int M, int Hd, int K) {
    extern __shared__ char smem[];
    const uint32_t sb = smem_u32(smem);
    const int tid = threadIdx.x;
    const int wid = tid >> 5, lane = tid & 31;
    const int lq = lane >> 2, lr = lane & 3;
    const int warp_m = wid >> 1, warp_n = wid & 1;
    const int m0 = blockIdx.y * CTA_M;
    const int n0 = blockIdx.x * CTA_C;
    const int NCH = K / KC;                        // 12

    float acc[4][8][4];
    #pragma unroll
    for (int tm = 0; tm < 4; tm++)
        #pragma unroll
        for (int tn = 0; tn < 8; tn++)
            #pragma unroll
            for (int q = 0; q < 4; q++) acc[tm][tn][q] = 0.0f;

    // ldmatrix per-lane address components (16B granules, XOR-8 swizzle per row)
    const int a_rowoff = ((lane >> 3) & 1) * 8 + (lane & 7);
    const int a_gran   = lane >> 4;                // 0/1
    const int a_row    = warp_m * 64 + a_rowoff;   // + tm*16
    const uint32_t a_base0 = (uint32_t)a_row * 128;
    const int a_rsw = a_row & 7;                   // tm*16/warp_m*64 keep &7
    const int b_row  = warp_n * 64 + (lane >> 4) * 8 + (lane & 7);  // + tnp*16
    const int b_gran = (lane >> 3) & 1;
    const uint32_t b_base0 = (uint32_t)b_row * 128;
    const int b_rsw = b_row & 7;

    auto load_chunk = [&](int c, int buf) {
        const uint32_t ab = sb + buf * BUF_BYTES;
        const uint32_t bb = ab + ABUF_BYTES;
        const int k0 = c * KC;
        // A: 128 rows x 8 granules = 1024 -> 8/thread
        #pragma unroll
        for (int t = 0; t < 8; t++) {
            int idx = tid + t * 128;
            int row = idx >> 3, g = idx & 7;
            CP_ASYNC16(ab + row * 128 + ((g ^ (row & 7)) << 4),
                       A + (size_t)(m0 + row) * K + k0 + g * 8);
        }
        // B: 128 rows x 8 granules = 1024 -> 8/thread; interleaved a/g rows
        #pragma unroll
        for (int t = 0; t < 8; t++) {
            int idx = tid + t * 128;
            int row = idx >> 3, g = idx & 7;
            int wrow = ((row & 1) ? Hd : 0) + n0 + (row >> 1);
            CP_ASYNC16(bb + row * 128 + ((g ^ (row & 7)) << 4),
                       W + (size_t)wrow * K + k0 + g * 8);
        }
        asm volatile("cp.async.commit_group;" ::: "memory");
    };

    load_chunk(0, 0);
    load_chunk(1, 1);

    for (int c = 0; c < NCH; c++) {
        const int buf = c % NSTAGE;
        if (c + 1 < NCH) {
            asm volatile("cp.async.wait_group 1;" ::: "memory");
        } else {
            asm volatile("cp.async.wait_group 0;" ::: "memory");
        }
        __syncthreads();
        // all threads are past compute(c-1) -> buffer (c+2)%NSTAGE is free
        if (c + 2 < NCH) load_chunk(c + 2, (c + 2) % NSTAGE);

        const uint32_t ab = sb + buf * BUF_BYTES;
        const uint32_t bb = ab + ABUF_BYTES;

        // ks-level double-buffered fragments
        uint32_t af[2][4][4];                      // [parity][tm][frag]
        uint32_t bfr[2][4][4];                     // [parity][tnp][frag]

        // preload fragments for ks = 0
        #pragma unroll
        for (int tm = 0; tm < 4; tm++) {
            uint32_t addr = ab + a_base0 + (uint32_t)(tm * 16 * 128)
                          + (uint32_t)((a_gran ^ a_rsw) << 4);
            LDSM_X4(af[0][tm], addr);
        }
        #pragma unroll
        for (int tnp = 0; tnp < 4; tnp++) {
            uint32_t addr = bb + b_base0 + (uint32_t)(tnp * 16 * 128)
                          + (uint32_t)((b_gran ^ b_rsw) << 4);
            LDSM_X4(bfr[0][tnp], addr);
        }

        #pragma unroll
        for (int ks = 0; ks < 4; ks++) {           // 4 x k16 per chunk
            const int cur = ks & 1, nxt = cur ^ 1;
            if (ks < 3) {
                #pragma unroll
                for (int tm = 0; tm < 4; tm++) {
                    uint32_t addr = ab + a_base0 + (uint32_t)(tm * 16 * 128)
                                  + (uint32_t)((((2 * (ks + 1) + a_gran) ^ a_rsw)) << 4);
                    LDSM_X4(af[nxt][tm], addr);
                }
                #pragma unroll
                for (int tnp = 0; tnp < 4; tnp++) {
                    uint32_t addr = bb + b_base0 + (uint32_t)(tnp * 16 * 128)
                                  + (uint32_t)((((2 * (ks + 1) + b_gran) ^ b_rsw)) << 4);
                    LDSM_X4(bfr[nxt][tnp], addr);
                }
            }
            #pragma unroll
            for (int tnp = 0; tnp < 4; tnp++) {
                #pragma unroll
                for (int tm = 0; tm < 4; tm++) {
                    MMA_BF16(acc[tm][2 * tnp],     af[cur][tm], bfr[cur][tnp][0], bfr[cur][tnp][1]);
                    MMA_BF16(acc[tm][2 * tnp + 1], af[cur][tm], bfr[cur][tnp][2], bfr[cur][tnp][3]);
                }
            }
        }
    }

    // epilogue: accum cols (2lr, 2lr+1) are the (a, g) GLU pair of out col tn*4+lr
    #pragma unroll
    for (int tm = 0; tm < 4; tm++) {
        const int mrow = m0 + warp_m * 64 + tm * 16 + lq;
        #pragma unroll
        for (int tn = 0; tn < 8; tn++) {
            const int col = n0 + warp_n * 32 + tn * 4 + lr;
            const float ba = bias[col], bg = bias[Hd + col];
            {
                float a = acc[tm][tn][0] + ba;
                float g = acc[tm][tn][1] + bg;
                out[(size_t)mrow * Hd + col] =
                    a / (1.0f + expf(-g)) + x[(size_t)mrow * Hd + col];
            }
            {
                float a = acc[tm][tn][2] + ba;
                float g = acc[tm][tn][3] + bg;
                out[(size_t)(mrow + 8) * Hd + col] =
                    a / (1.0f + expf(-g)) + x[(size_t)(mrow + 8) * Hd + col];
            }
        }
    }
}

// ---------------- launch ------------------------------------------------------
extern "C" void kernel_launch(void* const* d_in, const int* in_sizes, int n_in,
                              void* d_out, int out_size) {
    const float* x    = (const float*)d_in[0];   // (B, S, H)
    const float* kern = (const float*)d_in[1];   // (1, H, S)
    const float* D    = (const float*)d_in[2];   // (1, H)
    const float* W    = (const float*)d_in[3];   // (2H, H)
    const float* bias = (const float*)d_in[4];   // (2H,)
    float* out        = (float*)d_out;

    const int H  = in_sizes[2];                  // 768
    const int S  = in_sizes[1] / H;              // 8192
    const int M  = in_sizes[0] / H;              // 65536
    const int K  = H;
    const int total = M * H;

    __nv_bfloat16* act; cudaGetSymbolAddress((void**)&act, g_actb);
    __nv_bfloat16* wb;  cudaGetSymbolAddress((void**)&wb,  g_wb);

    build_taps_kernel<<<H, 256>>>(kern, S);
    conv_w_kernel<<<(2 * H * K / 4 + 255) / 256, 256>>>(W, wb, 2 * H * K / 4);
    act_kernel<<<(total / 4 + 255) / 256, 256>>>(x, D, act, total / 4, H, S);

    cudaFuncSetAttribute(gemm_glu_mma, cudaFuncAttributeMaxDynamicSharedMemorySize,
                         SMEM_GEMM);
    dim3 grid(H / CTA_C, M / CTA_M);             // (12, 512)
    gemm_glu_mma<<<grid, 128, SMEM_GEMM>>>(act, wb, bias, x, out, M, H, K);
}

// round 15
// speedup vs baseline: 1.2429x; 1.2429x over previous
#include <cuda_runtime.h>
#include <cuda_bf16.h>
#include <math.h>
#include <stdint.h>

// Problem worst-case sizing
#define MAXB 8
#define MAXS 8192
#define MAXH 768
#define MAXBS (MAXB * MAXS)          // 65536 rows

// ---------------- static device scratch ----------------
__device__ __nv_bfloat16 g_actb[(size_t)MAXBS * MAXH];      // bf16 silu activations (~100 MB)
__device__ __nv_bfloat16 g_wb[(size_t)(2 * MAXH) * MAXH];   // bf16 W (~2.4 MB)
__device__ int   g_tapPos[(size_t)MAXH * MAXS];
__device__ float g_tapVal[(size_t)MAXH * MAXS];
__device__ int   g_tapCnt[MAXH];

#define LAM 0.1f

#define CP_ASYNC16(dst, src) \
    asm volatile("cp.async.cg.shared.global [%0], [%1], 16;" :: "r"(dst), "l"(src) : "memory")

__device__ __forceinline__ uint32_t smem_u32(const void* p) {
    uint32_t a;
    asm("{ .reg .u64 t; cvta.to.shared.u64 t, %1; cvt.u32.u64 %0, t; }" : "=r"(a) : "l"(p));
    return a;
}

#define LDSM_X4(r, addr)                                                        \
    asm volatile("ldmatrix.sync.aligned.m8n8.x4.shared.b16 {%0,%1,%2,%3}, [%4];" \
        : "=r"((r)[0]), "=r"((r)[1]), "=r"((r)[2]), "=r"((r)[3]) : "r"(addr))

// mma m16n8k16 bf16, fp32 accum
#define MMA_BF16(c, a, b0, b1)                                                  \
    asm volatile(                                                               \
        "mma.sync.aligned.m16n8k16.row.col.f32.bf16.bf16.f32 "                  \
        "{%0,%1,%2,%3}, {%4,%5,%6,%7}, {%8,%9}, {%0,%1,%2,%3};"                 \
        : "+f"((c)[0]), "+f"((c)[1]), "+f"((c)[2]), "+f"((c)[3])                \
        : "r"((a)[0]), "r"((a)[1]), "r"((a)[2]), "r"((a)[3]),                   \
          "r"(b0), "r"(b1))

// ---------------- 1) threshold kernel -> sparse tap lists --------------------
__global__ void build_taps_kernel(const float* __restrict__ kern, int L) {
    int h = blockIdx.x;
    if (threadIdx.x == 0) g_tapCnt[h] = 0;
    __syncthreads();
    const float* kr = kern + (size_t)h * L;
    for (int j = threadIdx.x; j < L; j += blockDim.x) {
        float kv = kr[j];
        float a = fabsf(kv) - LAM;
        if (a > 0.0f) {
            float val = copysignf(a, kv);
            int idx = atomicAdd(&g_tapCnt[h], 1);
            g_tapPos[(size_t)h * L + idx] = j;
            g_tapVal[(size_t)h * L + idx] = val;
        }
    }
}

// ---------------- 1b) convert W to bf16 ----------------
__global__ void conv_w_kernel(const float* __restrict__ W, __nv_bfloat16* __restrict__ Wb, int n4) {
    int i = blockIdx.x * blockDim.x + threadIdx.x;
    if (i >= n4) return;
    float4 v = *(const float4*)(W + i * 4);
    __nv_bfloat162* o = (__nv_bfloat162*)(Wb + i * 4);
    o[0] = __floats2bfloat162_rn(v.x, v.y);
    o[1] = __floats2bfloat162_rn(v.z, v.w);
}

// ---------------- 2) activation: sparse conv + skip + silu -> bf16 -----------
__global__ void act_kernel(const float* __restrict__ x, const float* __restrict__ D,
                           __nv_bfloat16* __restrict__ act, int total4, int H, int S) {
    int i = blockIdx.x * blockDim.x + threadIdx.x;
    if (i >= total4) return;
    int base = i * 4;
    int h  = base % H;
    int bl = base / H;
    float4 xv = *(const float4*)(x + base);
    float4 dv = *(const float4*)(D + h);
    float v[4] = {xv.x * dv.x, xv.y * dv.y, xv.z * dv.z, xv.w * dv.w};
    int cnt[4] = {g_tapCnt[h], g_tapCnt[h + 1], g_tapCnt[h + 2], g_tapCnt[h + 3]};
    if (cnt[0] | cnt[1] | cnt[2] | cnt[3]) {
        int l = bl % S;
        int b = bl / S;
        const float* xb = x + (size_t)b * S * H;
        #pragma unroll
        for (int q = 0; q < 4; q++) {
            const int*   tp = g_tapPos + (size_t)(h + q) * S;
            const float* tv = g_tapVal + (size_t)(h + q) * S;
            for (int t = 0; t < cnt[q]; t++) {
                int j = tp[t];
                if (j <= l) v[q] += tv[t] * xb[(size_t)(l - j) * H + h + q];
            }
        }
    }
    float o0 = v[0] / (1.0f + expf(-v[0]));
    float o1 = v[1] / (1.0f + expf(-v[1]));
    float o2 = v[2] / (1.0f + expf(-v[2]));
    float o3 = v[3] / (1.0f + expf(-v[3]));
    __nv_bfloat162* op = (__nv_bfloat162*)(act + base);
    op[0] = __floats2bfloat162_rn(o0, o1);
    op[1] = __floats2bfloat162_rn(o2, o3);
}

// ---------------- 3) bf16 mma.sync GEMM + GLU + residual ---------------------
// CTA: 128 M-rows x 64 out-cols, 256 threads = 8 warps (4 m x 2 n), 2 CTAs/SM.
// Warp tile 32 x 64 (R13 shape). B tile = 128 interleaved rows (even=Wa, odd=Wg).
// K-chunk = 64 halves, 3-stage cp.async pipeline, rolling fragment prefetch
// across chunk boundaries; cp.async issued mid-chunk (ks==1).
#define CTA_M 128
#define CTA_C 64
#define KC    64                                   // bf16 halves per chunk
#define ABUF_BYTES (CTA_M * KC * 2)                // 16 KB
#define BBUF_BYTES (2 * CTA_C * KC * 2)            // 16 KB
#define BUF_BYTES  (ABUF_BYTES + BBUF_BYTES)       // 32 KB
#define NSTAGE 3
#define SMEM_GEMM  (NSTAGE * BUF_BYTES)            // 96 KB

__global__ __launch_bounds__(256, 2)
void gemm_glu_mma(const __nv_bfloat16* __restrict__ A, const __nv_bfloat16* __restrict__ W,
                  const float* __restrict__ bias, const float* __restrict__ x,
                  float* __restrict__ out, int M, int Hd, int K) {
    extern __shared__ char smem[];
    const uint32_t sb = smem_u32(smem);
    const int tid = threadIdx.x;
    const int wid = tid >> 5, lane = tid & 31;
    const int lq = lane >> 2, lr = lane & 3;
    const int warp_m = wid >> 1, warp_n = wid & 1;
    const int m0 = blockIdx.y * CTA_M;
    const int n0 = blockIdx.x * CTA_C;
    const int NCH = K / KC;                        // 12

    float acc[2][8][4];
    #pragma unroll
    for (int tm = 0; tm < 2; tm++)
        #pragma unroll
        for (int tn = 0; tn < 8; tn++)
            #pragma unroll
            for (int q = 0; q < 4; q++) acc[tm][tn][q] = 0.0f;

    // ldmatrix per-lane address components (16B granules, XOR-8 swizzle per row)
    const int a_rowoff = ((lane >> 3) & 1) * 8 + (lane & 7);
    const int a_gran   = lane >> 4;                // 0/1
    const int a_row    = warp_m * 32 + a_rowoff;   // + tm*16
    const uint32_t a_base0 = (uint32_t)a_row * 128;
    const int a_rsw = a_row & 7;                   // tm*16 keeps &7
    const int b_row  = warp_n * 64 + (lane >> 4) * 8 + (lane & 7);  // + tnp*16
    const int b_gran = (lane >> 3) & 1;
    const uint32_t b_base0 = (uint32_t)b_row * 128;
    const int b_rsw = b_row & 7;

    auto load_chunk = [&](int c, int buf) {
        const uint32_t ab = sb + buf * BUF_BYTES;
        const uint32_t bb = ab + ABUF_BYTES;
        const int k0 = c * KC;
        #pragma unroll
        for (int t = 0; t < 4; t++) {
            int idx = tid + t * 256;
            int row = idx >> 3, g = idx & 7;
            CP_ASYNC16(ab + row * 128 + ((g ^ (row & 7)) << 4),
                       A + (size_t)(m0 + row) * K + k0 + g * 8);
        }
        #pragma unroll
        for (int t = 0; t < 4; t++) {
            int idx = tid + t * 256;
            int row = idx >> 3, g = idx & 7;
            int wrow = ((row & 1) ? Hd : 0) + n0 + (row >> 1);
            CP_ASYNC16(bb + row * 128 + ((g ^ (row & 7)) << 4),
                       W + (size_t)wrow * K + k0 + g * 8);
        }
        asm volatile("cp.async.commit_group;" ::: "memory");
    };

    // rolling fragment registers
    uint32_t af[2][2][4];                          // [parity(ks&1)][tm][frag]
    uint32_t bf0[2][4];                            // B tnp=0 frag, per parity
    uint32_t brot[2][4];                           // rotating B frags within step

    // fragment load helper: step (chunk cc, k-step kk) into parity p
    auto ld_frag = [&](int cc, int kk, int p) {
        const uint32_t ab1 = sb + (cc % NSTAGE) * BUF_BYTES;
        const uint32_t bb1 = ab1 + ABUF_BYTES;
        #pragma unroll
        for (int tm = 0; tm < 2; tm++)
            LDSM_X4(af[p][tm], ab1 + a_base0 + (uint32_t)(tm * 2048)
                     + (uint32_t)(((2 * kk + a_gran) ^ a_rsw) << 4));
        LDSM_X4(bf0[p], bb1 + b_base0
                 + (uint32_t)(((2 * kk + b_gran) ^ b_rsw) << 4));
    };

    // one k16 step: ks is a compile-time-style constant after inlining
    auto do_step = [&](int c, int ks) {
        const int par = ks & 1;
        const uint32_t ab = sb + (c % NSTAGE) * BUF_BYTES;
        const uint32_t bb = ab + ABUF_BYTES;

        if (ks == 1 && c + 2 < NCH) load_chunk(c + 2, (c + 2) % NSTAGE);
        if (ks == 3) {
            if (c + 1 < NCH) {
                asm volatile("cp.async.wait_group 1;" ::: "memory");
                __syncthreads();
                ld_frag(c + 1, 0, par ^ 1);        // next chunk, ks=0, parity 0
            }
        } else {
            ld_frag(c, ks + 1, par ^ 1);           // next step, same chunk
        }

        // current step's B tnp=0 (carried in) -> rotation slot 0
        brot[0][0] = bf0[par][0]; brot[0][1] = bf0[par][1];
        brot[0][2] = bf0[par][2]; brot[0][3] = bf0[par][3];

        #pragma unroll
        for (int tnp = 0; tnp < 4; tnp++) {
            const int bc = tnp & 1, bn = bc ^ 1;
            if (tnp < 3)
                LDSM_X4(brot[bn], bb + b_base0 + (uint32_t)((tnp + 1) * 2048)
                         + (uint32_t)(((2 * ks + b_gran) ^ b_rsw) << 4));
            MMA_BF16(acc[0][2 * tnp],     af[par][0], brot[bc][0], brot[bc][1]);
            MMA_BF16(acc[1][2 * tnp],     af[par][1], brot[bc][0], brot[bc][1]);
            MMA_BF16(acc[0][2 * tnp + 1], af[par][0], brot[bc][2], brot[bc][3]);
            MMA_BF16(acc[1][2 * tnp + 1], af[par][1], brot[bc][2], brot[bc][3]);
        }
    };

    // prologue: 2 chunks in flight, wait chunk 0, preload step-0 fragments
    load_chunk(0, 0);
    load_chunk(1, 1);
    asm volatile("cp.async.wait_group 1;" ::: "memory");
    __syncthreads();
    ld_frag(0, 0, 0);

    for (int c = 0; c < NCH; c++) {
        do_step(c, 0);
        do_step(c, 1);
        do_step(c, 2);
        do_step(c, 3);
    }

    // epilogue: accum cols (2lr, 2lr+1) are the (a, g) GLU pair of out col tn*4+lr
    #pragma unroll
    for (int tm = 0; tm < 2; tm++) {
        const int mrow = m0 + warp_m * 32 + tm * 16 + lq;
        #pragma unroll
        for (int tn = 0; tn < 8; tn++) {
            const int col = n0 + warp_n * 32 + tn * 4 + lr;
            const float ba = bias[col], bg = bias[Hd + col];
            {
                float a = acc[tm][tn][0] + ba;
                float g = acc[tm][tn][1] + bg;
                out[(size_t)mrow * Hd + col] =
                    a / (1.0f + expf(-g)) + x[(size_t)mrow * Hd + col];
            }
            {
                float a = acc[tm][tn][2] + ba;
                float g = acc[tm][tn][3] + bg;
                out[(size_t)(mrow + 8) * Hd + col] =
                    a / (1.0f + expf(-g)) + x[(size_t)(mrow + 8) * Hd + col];
            }
        }
    }
}

// ---------------- launch ------------------------------------------------------
extern "C" void kernel_launch(void* const* d_in, const int* in_sizes, int n_in,
                              void* d_out, int out_size) {
    const float* x    = (const float*)d_in[0];   // (B, S, H)
    const float* kern = (const float*)d_in[1];   // (1, H, S)
    const float* D    = (const float*)d_in[2];   // (1, H)
    const float* W    = (const float*)d_in[3];   // (2H, H)
    const float* bias = (const float*)d_in[4];   // (2H,)
    float* out        = (float*)d_out;

    const int H  = in_sizes[2];                  // 768
    const int S  = in_sizes[1] / H;              // 8192
    const int M  = in_sizes[0] / H;              // 65536
    const int K  = H;
    const int total = M * H;

    __nv_bfloat16* act; cudaGetSymbolAddress((void**)&act, g_actb);
    __nv_bfloat16* wb;  cudaGetSymbolAddress((void**)&wb,  g_wb);

    build_taps_kernel<<<H, 256>>>(kern, S);
    conv_w_kernel<<<(2 * H * K / 4 + 255) / 256, 256>>>(W, wb, 2 * H * K / 4);
    act_kernel<<<(total / 4 + 255) / 256, 256>>>(x, D, act, total / 4, H, S);

    cudaFuncSetAttribute(gemm_glu_mma, cudaFuncAttributeMaxDynamicSharedMemorySize,
                         SMEM_GEMM);
    dim3 grid(H / CTA_C, M / CTA_M);             // (12, 512)
    gemm_glu_mma<<<grid, 256, SMEM_GEMM>>>(act, wb, bias, x, out, M, H, K);
}

// round 16
// speedup vs baseline: 1.2629x; 1.0161x over previous
#include <cuda_runtime.h>
#include <cuda_bf16.h>
#include <math.h>
#include <stdint.h>

// Problem worst-case sizing
#define MAXB 8
#define MAXS 8192
#define MAXH 768
#define MAXBS (MAXB * MAXS)          // 65536 rows

// ---------------- static device scratch ----------------
__device__ __nv_bfloat16 g_actb[(size_t)MAXBS * MAXH];      // bf16 silu activations (~100 MB)
__device__ __nv_bfloat16 g_wb[(size_t)(2 * MAXH) * MAXH];   // bf16 W (~2.4 MB)
__device__ int   g_tapPos[(size_t)MAXH * MAXS];
__device__ float g_tapVal[(size_t)MAXH * MAXS];
__device__ int   g_tapCnt[MAXH];

#define LAM 0.1f

#define CP_ASYNC16(dst, src) \
    asm volatile("cp.async.cg.shared.global [%0], [%1], 16;" :: "r"(dst), "l"(src) : "memory")

__device__ __forceinline__ uint32_t smem_u32(const void* p) {
    uint32_t a;
    asm("{ .reg .u64 t; cvta.to.shared.u64 t, %1; cvt.u32.u64 %0, t; }" : "=r"(a) : "l"(p));
    return a;
}

#define LDSM_X4(r, addr)                                                        \
    asm volatile("ldmatrix.sync.aligned.m8n8.x4.shared.b16 {%0,%1,%2,%3}, [%4];" \
        : "=r"((r)[0]), "=r"((r)[1]), "=r"((r)[2]), "=r"((r)[3]) : "r"(addr))

// mma m16n8k16 bf16, fp32 accum
#define MMA_BF16(c, a, b0, b1)                                                  \
    asm volatile(                                                               \
        "mma.sync.aligned.m16n8k16.row.col.f32.bf16.bf16.f32 "                  \
        "{%0,%1,%2,%3}, {%4,%5,%6,%7}, {%8,%9}, {%0,%1,%2,%3};"                 \
        : "+f"((c)[0]), "+f"((c)[1]), "+f"((c)[2]), "+f"((c)[3])                \
        : "r"((a)[0]), "r"((a)[1]), "r"((a)[2]), "r"((a)[3]),                   \
          "r"(b0), "r"(b1))

// ---------------- 1) threshold kernel -> sparse tap lists --------------------
__global__ void zero_taps_kernel(int H) {
    int h = blockIdx.x * blockDim.x + threadIdx.x;
    if (h < H) g_tapCnt[h] = 0;
}

__global__ void build_taps_kernel(const float* __restrict__ kern, int L) {
    int h = blockIdx.x >> 2;
    int q = blockIdx.x & 3;
    int seg = L >> 2;
    int j0 = q * seg;
    const float* kr = kern + (size_t)h * L;
    for (int j = j0 + threadIdx.x; j < j0 + seg; j += blockDim.x) {
        float kv = kr[j];
        float a = fabsf(kv) - LAM;
        if (a > 0.0f) {
            float val = copysignf(a, kv);
            int idx = atomicAdd(&g_tapCnt[h], 1);
            g_tapPos[(size_t)h * L + idx] = j;
            g_tapVal[(size_t)h * L + idx] = val;
        }
    }
}

// ---------------- 1b) convert W to bf16 ----------------
__global__ void conv_w_kernel(const float* __restrict__ W, __nv_bfloat16* __restrict__ Wb, int n4) {
    int i = blockIdx.x * blockDim.x + threadIdx.x;
    if (i >= n4) return;
    float4 v = *(const float4*)(W + i * 4);
    __nv_bfloat162* o = (__nv_bfloat162*)(Wb + i * 4);
    o[0] = __floats2bfloat162_rn(v.x, v.y);
    o[1] = __floats2bfloat162_rn(v.z, v.w);
}

// ---------------- 2) activation: sparse conv + skip + silu -> bf16 -----------
__global__ void act_kernel(const float* __restrict__ x, const float* __restrict__ D,
                           __nv_bfloat16* __restrict__ act, int total4, int H, int S) {
    int i = blockIdx.x * blockDim.x + threadIdx.x;
    if (i >= total4) return;
    int base = i * 4;
    int h  = base % H;
    int bl = base / H;
    float4 xv = *(const float4*)(x + base);
    float4 dv = *(const float4*)(D + h);
    float v[4] = {xv.x * dv.x, xv.y * dv.y, xv.z * dv.z, xv.w * dv.w};
    int cnt[4] = {g_tapCnt[h], g_tapCnt[h + 1], g_tapCnt[h + 2], g_tapCnt[h + 3]};
    if (cnt[0] | cnt[1] | cnt[2] | cnt[3]) {
        int l = bl % S;
        int b = bl / S;
        const float* xb = x + (size_t)b * S * H;
        #pragma unroll
        for (int q = 0; q < 4; q++) {
            const int*   tp = g_tapPos + (size_t)(h + q) * S;
            const float* tv = g_tapVal + (size_t)(h + q) * S;
            for (int t = 0; t < cnt[q]; t++) {
                int j = tp[t];
                if (j <= l) v[q] += tv[t] * xb[(size_t)(l - j) * H + h + q];
            }
        }
    }
    float o0 = v[0] / (1.0f + expf(-v[0]));
    float o1 = v[1] / (1.0f + expf(-v[1]));
    float o2 = v[2] / (1.0f + expf(-v[2]));
    float o3 = v[3] / (1.0f + expf(-v[3]));
    __nv_bfloat162* op = (__nv_bfloat162*)(act + base);
    op[0] = __floats2bfloat162_rn(o0, o1);
    op[1] = __floats2bfloat162_rn(o2, o3);
}

// ---------------- 3) bf16 mma.sync GEMM + GLU + residual ---------------------
// CTA: 128 M-rows x 64 out-cols, 256 threads = 8 warps (4 m x 2 n), 2 CTAs/SM.
// Warp tile 32 x 64. B tile = 128 interleaved rows (even=Wa, odd=Wg).
// K-chunk = 64 halves, 3-stage cp.async (spread issue), rolling frag prefetch,
// smem-staged vectorized epilogue.
#define CTA_M 128
#define CTA_C 64
#define KC    64                                   // bf16 halves per chunk
#define ABUF_BYTES (CTA_M * KC * 2)                // 16 KB
#define BBUF_BYTES (2 * CTA_C * KC * 2)            // 16 KB
#define BUF_BYTES  (ABUF_BYTES + BBUF_BYTES)       // 32 KB
#define NSTAGE 3
#define SMEM_GEMM  (NSTAGE * BUF_BYTES)            // 96 KB
#define OPAD 68                                    // f32 stride for out staging

__global__ __launch_bounds__(256, 2)
void gemm_glu_mma(const __nv_bfloat16* __restrict__ A, const __nv_bfloat16* __restrict__ W,
                  const float* __restrict__ bias, const float* __restrict__ x,
                  float* __restrict__ out, int M, int Hd, int K) {
    extern __shared__ char smem[];
    const uint32_t sb = smem_u32(smem);
    const int tid = threadIdx.x;
    const int wid = tid >> 5, lane = tid & 31;
    const int lq = lane >> 2, lr = lane & 3;
    const int warp_m = wid >> 1, warp_n = wid & 1;
    const int m0 = blockIdx.y * CTA_M;
    const int n0 = blockIdx.x * CTA_C;
    const int NCH = K / KC;                        // 12

    float acc[2][8][4];
    #pragma unroll
    for (int tm = 0; tm < 2; tm++)
        #pragma unroll
        for (int tn = 0; tn < 8; tn++)
            #pragma unroll
            for (int q = 0; q < 4; q++) acc[tm][tn][q] = 0.0f;

    // ldmatrix per-lane address components (16B granules, XOR-8 swizzle per row)
    const int a_rowoff = ((lane >> 3) & 1) * 8 + (lane & 7);
    const int a_gran   = lane >> 4;                // 0/1
    const int a_row    = warp_m * 32 + a_rowoff;   // + tm*16
    const uint32_t a_base0 = (uint32_t)a_row * 128;
    const int a_rsw = a_row & 7;
    const int b_row  = warp_n * 64 + (lane >> 4) * 8 + (lane & 7);  // + tnp*16
    const int b_gran = (lane >> 3) & 1;
    const uint32_t b_base0 = (uint32_t)b_row * 128;
    const int b_rsw = b_row & 7;

    // quarter chunk load: 2 of the per-thread 8 cp.asyncs (t = 0..3)
    auto load_quarter = [&](int c, int buf, int t) {
        const uint32_t ab = sb + buf * BUF_BYTES;
        const int k0 = c * KC;
        if (t < 2) {
            // A: 128 rows x 8 granules = 1024 -> quarters t=0,1
            #pragma unroll
            for (int s = 0; s < 2; s++) {
                int idx = tid + (t * 2 + s) * 256;
                int row = idx >> 3, g = idx & 7;
                CP_ASYNC16(ab + row * 128 + ((g ^ (row & 7)) << 4),
                           A + (size_t)(m0 + row) * K + k0 + g * 8);
            }
        } else {
            // B: 128 interleaved rows -> quarters t=2,3
            const uint32_t bb = ab + ABUF_BYTES;
            #pragma unroll
            for (int s = 0; s < 2; s++) {
                int idx = tid + ((t - 2) * 2 + s) * 256;
                int row = idx >> 3, g = idx & 7;
                int wrow = ((row & 1) ? Hd : 0) + n0 + (row >> 1);
                CP_ASYNC16(bb + row * 128 + ((g ^ (row & 7)) << 4),
                           W + (size_t)wrow * K + k0 + g * 8);
            }
        }
        if (t == 3) asm volatile("cp.async.commit_group;" ::: "memory");
    };

    // rolling fragment registers
    uint32_t af[2][2][4];                          // [parity][tm][frag]
    uint32_t bf0[2][4];                            // B tnp=0 frag, per parity
    uint32_t brot[2][4];

    auto ld_frag = [&](int cc, int kk, int p) {
        const uint32_t ab1 = sb + (cc % NSTAGE) * BUF_BYTES;
        const uint32_t bb1 = ab1 + ABUF_BYTES;
        #pragma unroll
        for (int tm = 0; tm < 2; tm++)
            LDSM_X4(af[p][tm], ab1 + a_base0 + (uint32_t)(tm * 2048)
                     + (uint32_t)(((2 * kk + a_gran) ^ a_rsw) << 4));
        LDSM_X4(bf0[p], bb1 + b_base0
                 + (uint32_t)(((2 * kk + b_gran) ^ b_rsw) << 4));
    };

    auto do_step = [&](int c, int ks) {
        const int par = ks & 1;
        const uint32_t ab = sb + (c % NSTAGE) * BUF_BYTES;
        const uint32_t bb = ab + ABUF_BYTES;

        if (c + 2 < NCH) load_quarter(c + 2, (c + 2) % NSTAGE, ks);
        if (ks == 3) {
            if (c + 1 < NCH) {
                asm volatile("cp.async.wait_group 1;" ::: "memory");
                __syncthreads();
                ld_frag(c + 1, 0, par ^ 1);
            }
        } else {
            ld_frag(c, ks + 1, par ^ 1);
        }

        brot[0][0] = bf0[par][0]; brot[0][1] = bf0[par][1];
        brot[0][2] = bf0[par][2]; brot[0][3] = bf0[par][3];

        #pragma unroll
        for (int tnp = 0; tnp < 4; tnp++) {
            const int bc = tnp & 1, bn = bc ^ 1;
            if (tnp < 3)
                LDSM_X4(brot[bn], bb + b_base0 + (uint32_t)((tnp + 1) * 2048)
                         + (uint32_t)(((2 * ks + b_gran) ^ b_rsw) << 4));
            MMA_BF16(acc[0][2 * tnp],     af[par][0], brot[bc][0], brot[bc][1]);
            MMA_BF16(acc[1][2 * tnp],     af[par][1], brot[bc][0], brot[bc][1]);
            MMA_BF16(acc[0][2 * tnp + 1], af[par][0], brot[bc][2], brot[bc][3]);
            MMA_BF16(acc[1][2 * tnp + 1], af[par][1], brot[bc][2], brot[bc][3]);
        }
    };

    // prologue: 2 chunks in flight, wait chunk 0, preload step-0 fragments
    #pragma unroll
    for (int t = 0; t < 4; t++) load_quarter(0, 0, t);
    #pragma unroll
    for (int t = 0; t < 4; t++) load_quarter(1, 1, t);
    asm volatile("cp.async.wait_group 1;" ::: "memory");
    __syncthreads();
    ld_frag(0, 0, 0);

    for (int c = 0; c < NCH; c++) {
        do_step(c, 0);
        do_step(c, 1);
        do_step(c, 2);
        do_step(c, 3);
    }

    // ---------------- epilogue: GLU -> smem staging -> coalesced out ---------
    __syncthreads();                               // all smem tile reads done
    float* sout = (float*)smem;                    // [128][OPAD]
    #pragma unroll
    for (int tm = 0; tm < 2; tm++) {
        const int r0 = warp_m * 32 + tm * 16 + lq;
        #pragma unroll
        for (int tn = 0; tn < 8; tn++) {
            const int cl = warp_n * 32 + tn * 4 + lr;
            const float ba = bias[n0 + cl], bg = bias[Hd + n0 + cl];
            {
                float a = acc[tm][tn][0] + ba;
                float g = acc[tm][tn][1] + bg;
                sout[r0 * OPAD + cl] = a / (1.0f + expf(-g));
            }
            {
                float a = acc[tm][tn][2] + ba;
                float g = acc[tm][tn][3] + bg;
                sout[(r0 + 8) * OPAD + cl] = a / (1.0f + expf(-g));
            }
        }
    }
    __syncthreads();
    #pragma unroll
    for (int q = 0; q < 8; q++) {
        int idx = q * 256 + tid;                   // 0..2047 float4 slots
        int row = idx >> 4;                        // 0..127
        int cg  = idx & 15;                        // float4 group in 64 cols
        float4 v = *(float4*)&sout[row * OPAD + cg * 4];
        const size_t go = (size_t)(m0 + row) * Hd + n0 + cg * 4;
        float4 xv = *(const float4*)(x + go);
        v.x += xv.x; v.y += xv.y; v.z += xv.z; v.w += xv.w;
        *(float4*)(out + go) = v;
    }
}

// ---------------- launch ------------------------------------------------------
extern "C" void kernel_launch(void* const* d_in, const int* in_sizes, int n_in,
                              void* d_out, int out_size) {
    const float* x    = (const float*)d_in[0];   // (B, S, H)
    const float* kern = (const float*)d_in[1];   // (1, H, S)
    const float* D    = (const float*)d_in[2];   // (1, H)
    const float* W    = (const float*)d_in[3];   // (2H, H)
    const float* bias = (const float*)d_in[4];   // (2H,)
    float* out        = (float*)d_out;

    const int H  = in_sizes[2];                  // 768
    const int S  = in_sizes[1] / H;              // 8192
    const int M  = in_sizes[0] / H;              // 65536
    const int K  = H;
    const int total = M * H;

    __nv_bfloat16* act; cudaGetSymbolAddress((void**)&act, g_actb);
    __nv_bfloat16* wb;  cudaGetSymbolAddress((void**)&wb,  g_wb);

    zero_taps_kernel<<<(H + 255) / 256, 256>>>(H);
    build_taps_kernel<<<H * 4, 256>>>(kern, S);
    conv_w_kernel<<<(2 * H * K / 4 + 255) / 256, 256>>>(W, wb, 2 * H * K / 4);
    act_kernel<<<(total / 4 + 255) / 256, 256>>>(x, D, act, total / 4, H, S);

    cudaFuncSetAttribute(gemm_glu_mma, cudaFuncAttributeMaxDynamicSharedMemorySize,
                         SMEM_GEMM);
    dim3 grid(H / CTA_C, M / CTA_M);             // (12, 512)
    gemm_glu_mma<<<grid, 256, SMEM_GEMM>>>(act, wb, bias, x, out, M, H, K);
}